// round 3
// baseline (speedup 1.0000x reference)
#include <cuda_runtime.h>
#include <cstddef>

// Problem constants (from reference setup_inputs)
#define B      64
#define S      2048
#define D      768
#define D4     (D / 4)          // 192 float4 per row
#define POOL   32
#define L      8
#define NT     10
#define TOPK   4
#define T_OUT  (L + TOPK * L + 1 + S)   // 8 + 32 + 1 + 2048 = 2089
#define X_OFF  (L + TOPK * L + 1)       // 41

// Copy kernel tiling: each block handles one (b, chunk) tile of ROWS seq rows
#define ROWS   64
#define CHUNKS (S / ROWS)       // 32

// Deterministic partial-sum scratch: [B][CHUNKS][D] floats (6.3 MB)
__device__ float g_partial[(size_t)B * CHUNKS * D];

// -------------------------------------------------------------------------
// Kernel 1: copy x -> out[:, X_OFF:, :] (float4, fully coalesced) while
// accumulating the per-chunk column sums for the query reduction.
// Grid: (CHUNKS, B), Block: 192 threads (one float4 column each).
// -------------------------------------------------------------------------
__global__ __launch_bounds__(D4) void copy_reduce_kernel(
    const float4* __restrict__ x, float4* __restrict__ out)
{
    const int chunk = blockIdx.x;          // 0..CHUNKS-1
    const int b     = blockIdx.y;          // 0..B-1
    const int t     = threadIdx.x;         // 0..191

    const float4* __restrict__ xrow =
        x + ((size_t)b * S + (size_t)chunk * ROWS) * D4 + t;
    float4* __restrict__ orow =
        out + ((size_t)b * T_OUT + X_OFF + (size_t)chunk * ROWS) * D4 + t;

    float4 acc = make_float4(0.f, 0.f, 0.f, 0.f);

#pragma unroll 8
    for (int r = 0; r < ROWS; r++) {
        float4 v = xrow[(size_t)r * D4];
        orow[(size_t)r * D4] = v;
        acc.x += v.x; acc.y += v.y; acc.z += v.z; acc.w += v.w;
    }

    float4* p = reinterpret_cast<float4*>(g_partial);
    p[((size_t)b * CHUNKS + chunk) * D4 + t] = acc;
}

// -------------------------------------------------------------------------
// Kernel 2: one CTA per batch element.
//  - deterministic sum of CHUNKS partials -> query q[D] in smem
//  - sim[p] ∝ dot(q, key_p) * rsqrt(|key_p|^2 + eps)   (query-norm factor and
//    the /S of the mean are common positive scales -> irrelevant to top-k)
//  - top-4 argmax with lowest-index tie-break (matches jax.lax.top_k)
//  - write g-prompt rows, selected e-prompt rows, cls row
// Block: 256 threads (8 warps).
// -------------------------------------------------------------------------
__global__ __launch_bounds__(256) void select_write_kernel(
    const float*  __restrict__ g_prompts,
    const float*  __restrict__ e_prompts,
    const float*  __restrict__ e_keys,
    const float*  __restrict__ cls_token,
    const int*    __restrict__ task_id_p,
    float*        __restrict__ out)
{
    const int b   = blockIdx.x;
    const int tid = threadIdx.x;
    const int lane = tid & 31;
    const int warp = tid >> 5;             // 0..7

    __shared__ float q[D];
    __shared__ float sim[POOL];
    __shared__ int   sel[TOPK];

    // ---- deterministic query reduction (3 columns per thread) ----
#pragma unroll
    for (int j = 0; j < 3; j++) {
        const int d = tid + j * 256;
        const float* p = g_partial + (size_t)b * CHUNKS * D + d;
        float s = 0.f;
#pragma unroll
        for (int c = 0; c < CHUNKS; c++) s += p[(size_t)c * D];
        q[d] = s;
    }
    __syncthreads();

    // ---- similarity: warp w handles pools {w, w+8, w+16, w+24} ----
#pragma unroll
    for (int pi = 0; pi < POOL / 8; pi++) {
        const int p = warp + pi * 8;
        const float* key = e_keys + (size_t)p * D;
        float dot = 0.f, ksq = 0.f;
#pragma unroll
        for (int j = 0; j < D / 32; j++) {     // 24 iters
            const int d = lane + j * 32;
            const float k = key[d];
            dot += q[d] * k;
            ksq += k * k;
        }
#pragma unroll
        for (int off = 16; off > 0; off >>= 1) {
            dot += __shfl_xor_sync(0xFFFFFFFFu, dot, off);
            ksq += __shfl_xor_sync(0xFFFFFFFFu, ksq, off);
        }
        if (lane == 0)
            sim[p] = dot * rsqrtf(ksq + 1e-12f);
    }
    __syncthreads();

    // ---- top-4 (descending, lowest index on tie) ----
    if (tid == 0) {
        unsigned taken = 0u;
        for (int k = 0; k < TOPK; k++) {
            int   bi = -1;
            float bv = -3.4e38f;
            for (int p = 0; p < POOL; p++) {
                if ((taken >> p) & 1u) continue;
                if (sim[p] > bv) { bv = sim[p]; bi = p; }
            }
            sel[k] = bi;
            taken |= 1u << bi;
        }
    }
    __syncthreads();

    // ---- write the 41 small rows for this batch element ----
    float4* obase = reinterpret_cast<float4*>(out) + (size_t)b * T_OUT * D4;

    // g-prompt: rows [0, 8)
    const int task = *task_id_p;
    const float4* gsrc =
        reinterpret_cast<const float4*>(g_prompts + (size_t)task * L * D);
    for (int i = tid; i < L * D4; i += 256)
        obase[i] = gsrc[i];

    // e-prompts: rows [8, 40)
#pragma unroll
    for (int k = 0; k < TOPK; k++) {
        const float4* esrc =
            reinterpret_cast<const float4*>(e_prompts + (size_t)sel[k] * L * D);
        float4* edst = obase + (L + k * L) * D4;
        for (int i = tid; i < L * D4; i += 256)
            edst[i] = esrc[i];
    }

    // cls: row 40
    const float4* csrc = reinterpret_cast<const float4*>(cls_token);
    float4* cdst = obase + (L + TOPK * L) * D4;
    for (int i = tid; i < D4; i += 256)
        cdst[i] = csrc[i];
}

// -------------------------------------------------------------------------
// Launch
// -------------------------------------------------------------------------
extern "C" void kernel_launch(void* const* d_in, const int* in_sizes, int n_in,
                              void* d_out, int out_size)
{
    const float* x         = (const float*)d_in[0];   // [B,S,D]
    const float* g_prompts = (const float*)d_in[1];   // [NT,L,D]
    const float* e_prompts = (const float*)d_in[2];   // [POOL,L,D]
    const float* e_keys    = (const float*)d_in[3];   // [POOL,D]
    const float* cls_token = (const float*)d_in[4];   // [1,1,D]
    const int*   task_id   = (const int*)d_in[5];     // scalar
    float*       out       = (float*)d_out;           // [B,T_OUT,D]

    dim3 grid1(CHUNKS, B);
    copy_reduce_kernel<<<grid1, D4>>>(
        reinterpret_cast<const float4*>(x),
        reinterpret_cast<float4*>(out));

    select_write_kernel<<<B, 256>>>(
        g_prompts, e_prompts, e_keys, cls_token, task_id, out);
}

// round 5
// speedup vs baseline: 1.0506x; 1.0506x over previous
#include <cuda_runtime.h>
#include <cstddef>

// Problem constants (from reference setup_inputs)
#define B      64
#define S      2048
#define D      768
#define D4     (D / 4)          // 192 float4 per row
#define POOL   32
#define L      8
#define NT     10
#define TOPK   4
#define T_OUT  (L + TOPK * L + 1 + S)   // 2089
#define X_OFF  (L + TOPK * L + 1)       // 41

// Copy kernel tiling
#define ROWS   64
#define CHUNKS (S / ROWS)       // 32

// Scratch (deterministic, every slot written exactly once per launch)
__device__ float g_partial[(size_t)B * CHUNKS * D];   // per-(b,chunk) column sums
__device__ float g_query[(size_t)B * D];              // reduced query per b
__device__ int   g_sel[(size_t)B * TOPK];             // selected pool indices

// -------------------------------------------------------------------------
// Kernel 1: copy x -> out[:, X_OFF:, :] (float4, coalesced) + per-chunk
// column sums. Extra grid column (chunk == CHUNKS) writes the
// selection-independent rows (g-prompt + cls) so they hide under the copy.
// Grid: (CHUNKS+1, B), Block: 192 threads.
// -------------------------------------------------------------------------
__global__ __launch_bounds__(D4) void copy_reduce_kernel(
    const float4* __restrict__ x, float4* __restrict__ out,
    const float4* __restrict__ g_prompts, const float4* __restrict__ cls_token,
    const int* __restrict__ task_id_p)
{
    const int chunk = blockIdx.x;
    const int b     = blockIdx.y;
    const int t     = threadIdx.x;

    if (chunk == CHUNKS) {
        // static rows for this batch: g-prompt rows [0,8), cls row 40
        float4* obase = out + (size_t)b * T_OUT * D4;
        const int task = *task_id_p;
        const float4* gsrc = g_prompts + (size_t)task * L * D4;
#pragma unroll
        for (int i = 0; i < L; i++)
            obase[i * D4 + t] = gsrc[i * D4 + t];
        obase[(size_t)(L + TOPK * L) * D4 + t] = cls_token[t];
        return;
    }

    const float4* __restrict__ xrow =
        x + ((size_t)b * S + (size_t)chunk * ROWS) * D4 + t;
    float4* __restrict__ orow =
        out + ((size_t)b * T_OUT + X_OFF + (size_t)chunk * ROWS) * D4 + t;

    float4 acc = make_float4(0.f, 0.f, 0.f, 0.f);

#pragma unroll 16
    for (int r = 0; r < ROWS; r++) {
        float4 v = xrow[(size_t)r * D4];
        orow[(size_t)r * D4] = v;
        acc.x += v.x; acc.y += v.y; acc.z += v.z; acc.w += v.w;
    }

    float4* p = reinterpret_cast<float4*>(g_partial);
    p[((size_t)b * CHUNKS + chunk) * D4 + t] = acc;
}

// -------------------------------------------------------------------------
// Kernel 2a: reduce chunk partials -> query. Grid: (3, B), 256 threads.
// Each thread owns one column: 32 coalesced strided loads, one store.
// -------------------------------------------------------------------------
__global__ __launch_bounds__(256) void query_reduce_kernel()
{
    const int d = blockIdx.x * 256 + threadIdx.x;   // 0..767
    const int b = blockIdx.y;
    const float* p = g_partial + (size_t)b * CHUNKS * D + d;
    float s = 0.f;
#pragma unroll
    for (int c = 0; c < CHUNKS; c++) s += p[(size_t)c * D];
    g_query[(size_t)b * D + d] = s;
}

// -------------------------------------------------------------------------
// Kernel 2b: similarity + top-4 per batch. Grid: B, 256 threads (8 warps).
// Query-norm and /S are common positive scales -> irrelevant to ordering.
// -------------------------------------------------------------------------
__global__ __launch_bounds__(256) void select_kernel(
    const float* __restrict__ e_keys)
{
    const int b    = blockIdx.x;
    const int tid  = threadIdx.x;
    const int lane = tid & 31;
    const int warp = tid >> 5;

    __shared__ float q[D];
    __shared__ float sim[POOL];

    // stage query in smem
#pragma unroll
    for (int j = 0; j < 3; j++)
        q[tid + j * 256] = g_query[(size_t)b * D + tid + j * 256];
    __syncthreads();

    // warp w handles pools {w, w+8, w+16, w+24}
#pragma unroll
    for (int pi = 0; pi < POOL / 8; pi++) {
        const int p = warp + pi * 8;
        const float* key = e_keys + (size_t)p * D;
        float dot = 0.f, ksq = 0.f;
#pragma unroll
        for (int j = 0; j < D / 32; j++) {
            const int d = lane + j * 32;
            const float k = key[d];
            dot += q[d] * k;
            ksq += k * k;
        }
#pragma unroll
        for (int off = 16; off > 0; off >>= 1) {
            dot += __shfl_xor_sync(0xFFFFFFFFu, dot, off);
            ksq += __shfl_xor_sync(0xFFFFFFFFu, ksq, off);
        }
        if (lane == 0)
            sim[p] = dot * rsqrtf(ksq + 1e-12f);
    }
    __syncthreads();

    // top-4, descending, lowest index on tie (matches jax.lax.top_k)
    if (tid == 0) {
        unsigned taken = 0u;
        for (int k = 0; k < TOPK; k++) {
            int   bi = 0;
            float bv = -3.4e38f;
            for (int p = 0; p < POOL; p++) {
                if ((taken >> p) & 1u) continue;
                if (sim[p] > bv) { bv = sim[p]; bi = p; }
            }
            g_sel[b * TOPK + k] = bi;
            taken |= 1u << bi;
        }
    }
}

// -------------------------------------------------------------------------
// Kernel 3: write selected e-prompt rows. Grid: (TOPK*L, B), 192 threads.
// One block per output row -> full-chip parallelism for the 6.3 MB of writes.
// -------------------------------------------------------------------------
__global__ __launch_bounds__(D4) void eprompt_write_kernel(
    const float4* __restrict__ e_prompts, float4* __restrict__ out)
{
    const int r = blockIdx.x;              // 0..31 (row within the e-block)
    const int b = blockIdx.y;
    const int t = threadIdx.x;

    const int k   = r >> 3;                // which of the 4 selections
    const int lr  = r & 7;                 // row within the prompt block
    const int idx = g_sel[b * TOPK + k];

    const float4* src = e_prompts + ((size_t)idx * L + lr) * D4;
    float4* dst = out + ((size_t)b * T_OUT + L + r) * D4;
    dst[t] = src[t];
}

// -------------------------------------------------------------------------
// Launch
// -------------------------------------------------------------------------
extern "C" void kernel_launch(void* const* d_in, const int* in_sizes, int n_in,
                              void* d_out, int out_size)
{
    const float* x         = (const float*)d_in[0];   // [B,S,D]
    const float* g_prompts = (const float*)d_in[1];   // [NT,L,D]
    const float* e_prompts = (const float*)d_in[2];   // [POOL,L,D]
    const float* e_keys    = (const float*)d_in[3];   // [POOL,D]
    const float* cls_token = (const float*)d_in[4];   // [1,1,D]
    const int*   task_id   = (const int*)d_in[5];     // scalar
    float*       out       = (float*)d_out;           // [B,T_OUT,D]

    dim3 grid1(CHUNKS + 1, B);
    copy_reduce_kernel<<<grid1, D4>>>(
        reinterpret_cast<const float4*>(x),
        reinterpret_cast<float4*>(out),
        reinterpret_cast<const float4*>(g_prompts),
        reinterpret_cast<const float4*>(cls_token),
        task_id);

    dim3 grid2a(3, B);
    query_reduce_kernel<<<grid2a, 256>>>();

    select_kernel<<<B, 256>>>(e_keys);

    dim3 grid3(TOPK * L, B);
    eprompt_write_kernel<<<grid3, D4>>>(
        reinterpret_cast<const float4*>(e_prompts),
        reinterpret_cast<float4*>(out));
}